// round 16
// baseline (speedup 1.0000x reference)
#include <cuda_runtime.h>
#include <cuda_fp16.h>
#include <math.h>
#include <stdint.h>

// ---------------- problem dims ----------------
#define Bn    8
#define Sq    1024
#define Cdim  640
#define Tctx  77
#define CTXD  768
#define NHEAD 8
#define HSZ   80
#define FFD   5120
#define FFH   2560
#define Mrows (Bn * Sq)      // 8192
#define MCTX  (Bn * Tctx)    // 616

// ---------------- scratch ----------------
__device__ float  g_y   [(size_t)Mrows * Cdim];
__device__ float  g_t   [(size_t)Mrows * Cdim];
__device__ __half g_ln16[(size_t)Mrows * Cdim];
__device__ __half g_q16 [(size_t)Mrows * Cdim];
__device__ __half g_at16[(size_t)Mrows * Cdim];
__device__ __half g_t16 [(size_t)Mrows * Cdim];
__device__ __half g_ctx16[(size_t)MCTX * CTXD];
__device__ __half g_qkv16[(size_t)Mrows * 1920];
__device__ __half g_kv16 [(size_t)MCTX * 1280];
__device__ __half g_ff16 [(size_t)Mrows * FFD];
__device__ __half g_gg16 [(size_t)Mrows * FFH];
// transposed fp16 weights [N][K]
__device__ __half g_piwT[(size_t)Cdim * Cdim];
__device__ __half g_wpT [(size_t)1920 * Cdim];
__device__ __half g_a2qT[(size_t)Cdim * Cdim];
__device__ __half g_wcT [(size_t)1280 * CTXD];
__device__ __half g_a1oT[(size_t)Cdim * Cdim];
__device__ __half g_a2oT[(size_t)Cdim * Cdim];
__device__ __half g_ff1T[(size_t)FFD * Cdim];
__device__ __half g_ff2T[(size_t)Cdim * FFH];
__device__ __half g_prwT[(size_t)Cdim * Cdim];

// ---------------- helpers ----------------
__device__ __forceinline__ void mma_f16(float* c, const uint32_t* a, const uint32_t* b)
{
    asm volatile(
        "mma.sync.aligned.m16n8k16.row.col.f32.f16.f16.f32 "
        "{%0,%1,%2,%3}, {%4,%5,%6,%7}, {%8,%9}, {%0,%1,%2,%3};"
        : "+f"(c[0]), "+f"(c[1]), "+f"(c[2]), "+f"(c[3])
        : "r"(a[0]), "r"(a[1]), "r"(a[2]), "r"(a[3]), "r"(b[0]), "r"(b[1]));
}

__device__ __forceinline__ void cp16(uint32_t dst, const void* src, bool pred)
{
    const int sz = pred ? 16 : 0;
    asm volatile("cp.async.cg.shared.global [%0], [%1], 16, %2;\n"
                 :: "r"(dst), "l"(src), "r"(sz));
}
__device__ __forceinline__ void cp_commit() { asm volatile("cp.async.commit_group;\n"); }
template <int N>
__device__ __forceinline__ void cp_wait() { asm volatile("cp.async.wait_group %0;\n" :: "n"(N)); }

__device__ __forceinline__ uint32_t pack2(float a, float b)
{
    __half2 h = __floats2half2_rn(a, b);
    return *reinterpret_cast<uint32_t*>(&h);
}

// ---------------- fused weight transpose+convert: 12 jobs, one launch ----------------
// Each job: src fp32 [K][N] -> dst fp16 [N][K], 32x32 tiles, 256 threads.
#define SQ_TILES   400                 // (640/32)*(640/32)
#define WC_TILES   480                 // (768/32)*(640/32)
#define FF1_TILES  3200                // (640/32)*(5120/32)
#define FF2_TILES  1600                // (2560/32)*(640/32)
#define JOB_SQ_END   (8 * SQ_TILES)           // 3200
#define JOB_WC_END   (JOB_SQ_END + 2 * WC_TILES)   // 4160
#define JOB_FF1_END  (JOB_WC_END + FF1_TILES)      // 7360
#define WT_TOTAL     (JOB_FF1_END + FF2_TILES)     // 8960

__global__ void wTall_kernel(
    const float* __restrict__ piw, const float* __restrict__ a1q,
    const float* __restrict__ a1k, const float* __restrict__ a1v,
    const float* __restrict__ a2q, const float* __restrict__ a1o,
    const float* __restrict__ a2o, const float* __restrict__ prw,
    const float* __restrict__ a2k, const float* __restrict__ a2v,
    const float* __restrict__ ff1w, const float* __restrict__ ff2w,
    __half* __restrict__ piwT, __half* __restrict__ wpT,
    __half* __restrict__ a2qT, __half* __restrict__ a1oT,
    __half* __restrict__ a2oT, __half* __restrict__ prwT,
    __half* __restrict__ wcT,  __half* __restrict__ ff1T,
    __half* __restrict__ ff2T)
{
    const int bid = blockIdx.x;
    const float* src;
    __half* dst;
    int K, N, t;
    if (bid < JOB_SQ_END) {
        const int j = bid / SQ_TILES;
        t = bid % SQ_TILES;
        K = Cdim; N = Cdim;
        const float* srcs[8] = { piw, a1q, a1k, a1v, a2q, a1o, a2o, prw };
        __half* dsts[8] = { piwT, wpT, wpT + (size_t)640 * Cdim,
                            wpT + (size_t)1280 * Cdim, a2qT, a1oT, a2oT, prwT };
        src = srcs[j]; dst = dsts[j];
    } else if (bid < JOB_WC_END) {
        const int j = (bid - JOB_SQ_END) / WC_TILES;
        t = (bid - JOB_SQ_END) % WC_TILES;
        K = CTXD; N = Cdim;
        src = j ? a2v : a2k;
        dst = wcT + (size_t)j * 640 * CTXD;
    } else if (bid < JOB_FF1_END) {
        t = bid - JOB_WC_END;
        K = Cdim; N = FFD;
        src = ff1w; dst = ff1T;
    } else {
        t = bid - JOB_FF1_END;
        K = FFH; N = Cdim;
        src = ff2w; dst = ff2T;
    }

    __shared__ float ts[32][33];
    const int ntx = N / 32;
    const int kt = (t / ntx) * 32, nt = (t % ntx) * 32;
    const int tx = threadIdx.x & 31, ty = threadIdx.x >> 5;
    #pragma unroll
    for (int r = ty; r < 32; r += 8)
        ts[r][tx] = src[(size_t)(kt + r) * N + nt + tx];
    __syncthreads();
    #pragma unroll
    for (int r = ty; r < 32; r += 8)
        dst[(size_t)(nt + r) * K + kt + tx] = __float2half(ts[tx][r]);
}

// ---------------- fp32 -> fp16 (count multiple of 4) ----------------
__global__ void f2h_kernel(const float* __restrict__ in, __half* __restrict__ out, int n4)
{
    const int i = blockIdx.x * blockDim.x + threadIdx.x;
    if (i >= n4) return;
    const float4 v = *reinterpret_cast<const float4*>(in + (size_t)i * 4);
    uint2 u; u.x = pack2(v.x, v.y); u.y = pack2(v.z, v.w);
    *reinterpret_cast<uint2*>(out + (size_t)i * 4) = u;
}

// ---------------- GroupNorm (fp32 in, fp16 out) ----------------
__global__ void groupnorm_kernel(const float* __restrict__ x,
                                 const float* __restrict__ gamma,
                                 const float* __restrict__ beta,
                                 __half* __restrict__ out)
{
    const int b = blockIdx.x >> 5;
    const int g = blockIdx.x & 31;
    const float* base = x + (size_t)b * Sq * Cdim + g * 20;
    float sum = 0.f, sq = 0.f;
    for (int idx = threadIdx.x; idx < Sq * 20; idx += 256) {
        int hw = idx / 20, c = idx % 20;
        float v = base[(size_t)hw * Cdim + c];
        sum += v; sq += v * v;
    }
    #pragma unroll
    for (int o = 16; o > 0; o >>= 1) {
        sum += __shfl_xor_sync(0xffffffffu, sum, o);
        sq  += __shfl_xor_sync(0xffffffffu, sq,  o);
    }
    __shared__ float s1[8], s2[8];
    const int wid = threadIdx.x >> 5, lane = threadIdx.x & 31;
    if (lane == 0) { s1[wid] = sum; s2[wid] = sq; }
    __syncthreads();
    float tot = 0.f, totq = 0.f;
    #pragma unroll
    for (int i = 0; i < 8; i++) { tot += s1[i]; totq += s2[i]; }
    const float mean = tot * (1.f / 20480.f);
    const float var  = totq * (1.f / 20480.f) - mean * mean;
    const float rstd = rsqrtf(var + 1e-5f);
    __half* ob = out + (size_t)b * Sq * Cdim + g * 20;
    for (int idx = threadIdx.x; idx < Sq * 20; idx += 256) {
        int hw = idx / 20, c = idx % 20;
        float v = base[(size_t)hw * Cdim + c];
        ob[(size_t)hw * Cdim + c] =
            __float2half((v - mean) * rstd * gamma[g * 20 + c] + beta[g * 20 + c]);
    }
}

// ---------------- LayerNorm (fp32 in, fp16 out) ----------------
__global__ void layernorm_kernel(const float* __restrict__ x,
                                 const float* __restrict__ g,
                                 const float* __restrict__ b,
                                 __half* __restrict__ out, int rows)
{
    const int w = (blockIdx.x << 3) + (threadIdx.x >> 5);
    if (w >= rows) return;
    const int lane = threadIdx.x & 31;
    const float* row = x + (size_t)w * Cdim;
    float4 v[5];
    float sum = 0.f, sq = 0.f;
    #pragma unroll
    for (int p = 0; p < 5; p++) {
        v[p] = *reinterpret_cast<const float4*>(row + (lane + 32 * p) * 4);
        sum += v[p].x + v[p].y + v[p].z + v[p].w;
        sq  += v[p].x * v[p].x + v[p].y * v[p].y + v[p].z * v[p].z + v[p].w * v[p].w;
    }
    #pragma unroll
    for (int o = 16; o > 0; o >>= 1) {
        sum += __shfl_xor_sync(0xffffffffu, sum, o);
        sq  += __shfl_xor_sync(0xffffffffu, sq,  o);
    }
    const float mean = sum * (1.f / 640.f);
    const float var  = sq * (1.f / 640.f) - mean * mean;
    const float rstd = rsqrtf(var + 1e-5f);
    __half* orow = out + (size_t)w * Cdim;
    #pragma unroll
    for (int p = 0; p < 5; p++) {
        const int off = (lane + 32 * p) * 4;
        const float4 g4 = *reinterpret_cast<const float4*>(g + off);
        const float4 b4 = *reinterpret_cast<const float4*>(b + off);
        uint2 u;
        u.x = pack2((v[p].x - mean) * rstd * g4.x + b4.x,
                    (v[p].y - mean) * rstd * g4.y + b4.y);
        u.y = pack2((v[p].z - mean) * rstd * g4.z + b4.z,
                    (v[p].w - mean) * rstd * g4.w + b4.w);
        *reinterpret_cast<uint2*>(orow + off) = u;
    }
}

// ---------------- pipelined FP16 GEMM (BK = 64 halfs) ----------------
#define HP   72
#define HP2  36
#define STGH (128 * HP)
#define STGB (STGH * 2)
#define NSTAGE 3
#define GEMM_SMEM (NSTAGE * 2 * STGB)

__global__ __launch_bounds__(256, 2)
void hgemm_kernel(const __half* __restrict__ A, const __half* __restrict__ Bt,
                  const float* __restrict__ bias, const float* __restrict__ Res,
                  float* __restrict__ C32, __half* __restrict__ C16,
                  int M, int N, int K)
{
    extern __shared__ __half smem[];
    __half* As = smem;
    __half* Bs = smem + NSTAGE * STGH;
    const int tid  = threadIdx.x;
    const int lane = tid & 31, warp = tid >> 5;
    const int g = lane >> 2, tig = lane & 3;
    const int wm = (warp >> 2) * 64;
    const int wn = (warp & 3) * 32;
    const int row0 = blockIdx.y * 128, col0 = blockIdx.x * 128;

    // staging: 2 threads per row, 32 halfs (4 x cp16) each
    const int srow = tid >> 1, soff = (tid & 1) * 32;
    const bool arow_ok = (row0 + srow) < M;
    const __half* agp = A  + (size_t)(row0 + srow) * K + soff;
    const __half* bgp = Bt + (size_t)(col0 + srow) * K + soff;
    const uint32_t as_d = (uint32_t)__cvta_generic_to_shared(As + srow * HP + soff);
    const uint32_t bs_d = (uint32_t)__cvta_generic_to_shared(Bs + srow * HP + soff);

    float acc[4][4][4];
    #pragma unroll
    for (int mt = 0; mt < 4; mt++)
        #pragma unroll
        for (int nt = 0; nt < 4; nt++)
            #pragma unroll
            for (int i = 0; i < 4; i++) acc[mt][nt][i] = 0.f;

    const int KT = K >> 6;   // 64 halfs per tile

    #pragma unroll
    for (int p = 0; p < 2; p++) {
        if (p < KT) {
            const __half* ag = agp + p * 64;
            const __half* bg = bgp + p * 64;
            #pragma unroll
            for (int l = 0; l < 4; l++) cp16(as_d + (uint32_t)(p * STGB) + l * 16, ag + l * 8, arow_ok);
            #pragma unroll
            for (int l = 0; l < 4; l++) cp16(bs_d + (uint32_t)(p * STGB) + l * 16, bg + l * 8, true);
        }
        cp_commit();
    }

    int s = 0, sw = 2;
    for (int kt = 0; kt < KT; kt++) {
        cp_wait<1>();
        __syncthreads();

        if (kt + 2 < KT) {
            const __half* ag = agp + (kt + 2) * 64;
            const __half* bg = bgp + (kt + 2) * 64;
            const uint32_t ad = as_d + (uint32_t)(sw * STGB);
            const uint32_t bd = bs_d + (uint32_t)(sw * STGB);
            #pragma unroll
            for (int l = 0; l < 4; l++) cp16(ad + l * 16, ag + l * 8, arow_ok);
            #pragma unroll
            for (int l = 0; l < 4; l++) cp16(bd + l * 16, bg + l * 8, true);
        }
        cp_commit();

        const uint32_t* as32 = reinterpret_cast<const uint32_t*>(As + s * STGH);
        const uint32_t* bs32 = reinterpret_cast<const uint32_t*>(Bs + s * STGH);
        #pragma unroll
        for (int ks = 0; ks < 4; ks++) {
            const int k2 = ks * 8 + tig;
            uint32_t af[4][4];
            #pragma unroll
            for (int mt = 0; mt < 4; mt++) {
                const int m = wm + mt * 16 + g;
                af[mt][0] = as32[m * HP2 + k2];
                af[mt][1] = as32[(m + 8) * HP2 + k2];
                af[mt][2] = as32[m * HP2 + k2 + 4];
                af[mt][3] = as32[(m + 8) * HP2 + k2 + 4];
            }
            uint32_t bf[4][2];
            #pragma unroll
            for (int nt = 0; nt < 4; nt++) {
                const int n = wn + nt * 8 + g;
                bf[nt][0] = bs32[n * HP2 + k2];
                bf[nt][1] = bs32[n * HP2 + k2 + 4];
            }
            #pragma unroll
            for (int mt = 0; mt < 4; mt++)
                #pragma unroll
                for (int nt = 0; nt < 4; nt++)
                    mma_f16(acc[mt][nt], af[mt], bf[nt]);
        }

        s = (s == NSTAGE - 1) ? 0 : s + 1;
        sw = (sw == NSTAGE - 1) ? 0 : sw + 1;
    }

    #pragma unroll
    for (int mt = 0; mt < 4; mt++) {
        const int r0 = row0 + wm + mt * 16 + g;
        const int r1 = r0 + 8;
        #pragma unroll
        for (int nt = 0; nt < 4; nt++) {
            const int c = col0 + wn + nt * 8 + 2 * tig;
            float2 v0 = make_float2(acc[mt][nt][0], acc[mt][nt][1]);
            float2 v1 = make_float2(acc[mt][nt][2], acc[mt][nt][3]);
            if (bias) {
                const float2 bb = *reinterpret_cast<const float2*>(bias + c);
                v0.x += bb.x; v0.y += bb.y;
                v1.x += bb.x; v1.y += bb.y;
            }
            if (r0 < M) {
                if (Res) {
                    const float2 rv = *reinterpret_cast<const float2*>(Res + (size_t)r0 * N + c);
                    v0.x += rv.x; v0.y += rv.y;
                }
                if (C32) *reinterpret_cast<float2*>(C32 + (size_t)r0 * N + c) = v0;
                if (C16) *reinterpret_cast<uint32_t*>(C16 + (size_t)r0 * N + c) = pack2(v0.x, v0.y);
            }
            if (r1 < M) {
                if (Res) {
                    const float2 rv = *reinterpret_cast<const float2*>(Res + (size_t)r1 * N + c);
                    v1.x += rv.x; v1.y += rv.y;
                }
                if (C32) *reinterpret_cast<float2*>(C32 + (size_t)r1 * N + c) = v1;
                if (C16) *reinterpret_cast<uint32_t*>(C16 + (size_t)r1 * N + c) = pack2(v1.x, v1.y);
            }
        }
    }
}

// ---------------- fused flash attention (fp16 in/out, fp32 softmax state) ----------------
// Block: 64 q-rows, 4 warps x 16 rows each; full 80-wide head per warp.
#define FQP  88
#define FQP2 44
#define FVP  72
#define FVP2 36
__global__ __launch_bounds__(128)
void flash_attn(const __half* __restrict__ Q, const __half* __restrict__ K,
                const __half* __restrict__ V, __half* __restrict__ O,
                int Tk, int qstr, int kstr, int kSeq)
{
    __shared__ __half Qs[64 * FQP];
    __shared__ __half Ks[64 * FQP];
    __shared__ __half Vs[80 * FVP];

    const int bh = blockIdx.y, b = bh >> 3, n = bh & 7;
    const __half* qb = Q + (size_t)b * Sq * qstr + n * HSZ;
    const __half* kb = K + (size_t)b * kSeq * kstr + n * HSZ;
    const __half* vb = V + (size_t)b * kSeq * kstr + n * HSZ;
    __half* ob = O + (size_t)b * Sq * Cdim + n * HSZ;
    const int i0 = blockIdx.x * 64;
    const int tid = threadIdx.x;
    const int lane = tid & 31, warp = tid >> 5;
    const int g = lane >> 2, tig = lane & 3;
    const int wq = warp * 16;

    // stage Q once
    for (int e = tid; e < 64 * 10; e += 128) {
        const int r = e / 10, c8 = (e % 10) * 8;
        *reinterpret_cast<uint4*>(&Qs[r * FQP + c8]) =
            *reinterpret_cast<const uint4*>(qb + (size_t)(i0 + r) * qstr + c8);
    }
    __syncthreads();

    // Q fragments: rows [wq, wq+16), 5 k16 chunks
    uint32_t qf[5][4];
    {
        const uint32_t* qs32 = reinterpret_cast<const uint32_t*>(Qs);
        #pragma unroll
        for (int ks = 0; ks < 5; ks++) {
            const int k2 = ks * 8 + tig;
            qf[ks][0] = qs32[(wq + g) * FQP2 + k2];
            qf[ks][1] = qs32[(wq + g + 8) * FQP2 + k2];
            qf[ks][2] = qs32[(wq + g) * FQP2 + k2 + 4];
            qf[ks][3] = qs32[(wq + g + 8) * FQP2 + k2 + 4];
        }
    }

    float m0 = -1e30f, m1 = -1e30f, l0 = 0.f, l1 = 0.f;
    float oacc[10][4];
    #pragma unroll
    for (int nt = 0; nt < 10; nt++)
        #pragma unroll
        for (int i = 0; i < 4; i++) oacc[nt][i] = 0.f;

    const float scale = 0.11180339887498949f;
    const int nT = (Tk + 63) / 64;

    for (int jt = 0; jt < nT; jt++) {
        __syncthreads();
        // stage K tile [64 x 80] and V^T tile [80 x 64]
        for (int e = tid; e < 64 * 10; e += 128) {
            const int r = e / 10, c8 = (e % 10) * 8;
            uint4 kv = make_uint4(0u, 0u, 0u, 0u);
            if (jt * 64 + r < Tk)
                kv = *reinterpret_cast<const uint4*>(kb + (size_t)(jt * 64 + r) * kstr + c8);
            *reinterpret_cast<uint4*>(&Ks[r * FQP + c8]) = kv;
            uint4 vv = make_uint4(0u, 0u, 0u, 0u);
            if (jt * 64 + r < Tk)
                vv = *reinterpret_cast<const uint4*>(vb + (size_t)(jt * 64 + r) * kstr + c8);
            const __half* vh = reinterpret_cast<const __half*>(&vv);
            #pragma unroll
            for (int i = 0; i < 8; i++)
                Vs[(c8 + i) * FVP + r] = vh[i];
        }
        __syncthreads();

        // S = scale * Q K^T  (16 x 64 per warp)
        float sacc[8][4];
        #pragma unroll
        for (int nt = 0; nt < 8; nt++)
            #pragma unroll
            for (int i = 0; i < 4; i++) sacc[nt][i] = 0.f;
        {
            const uint32_t* ks32 = reinterpret_cast<const uint32_t*>(Ks);
            #pragma unroll
            for (int ks = 0; ks < 5; ks++) {
                const int k2 = ks * 8 + tig;
                uint32_t bf[8][2];
                #pragma unroll
                for (int nt = 0; nt < 8; nt++) {
                    const int nn = nt * 8 + g;
                    bf[nt][0] = ks32[nn * FQP2 + k2];
                    bf[nt][1] = ks32[nn * FQP2 + k2 + 4];
                }
                #pragma unroll
                for (int nt = 0; nt < 8; nt++)
                    mma_f16(sacc[nt], qf[ks], bf[nt]);
            }
        }

        // scale + mask, row max
        float rm0 = -1e30f, rm1 = -1e30f;
        #pragma unroll
        for (int nt = 0; nt < 8; nt++) {
            const int cb = jt * 64 + nt * 8 + 2 * tig;
            sacc[nt][0] = (cb     < Tk) ? sacc[nt][0] * scale : -1e30f;
            sacc[nt][1] = (cb + 1 < Tk) ? sacc[nt][1] * scale : -1e30f;
            sacc[nt][2] = (cb     < Tk) ? sacc[nt][2] * scale : -1e30f;
            sacc[nt][3] = (cb + 1 < Tk) ? sacc[nt][3] * scale : -1e30f;
            rm0 = fmaxf(rm0, fmaxf(sacc[nt][0], sacc[nt][1]));
            rm1 = fmaxf(rm1, fmaxf(sacc[nt][2], sacc[nt][3]));
        }
        rm0 = fmaxf(rm0, __shfl_xor_sync(0xffffffffu, rm0, 1));
        rm0 = fmaxf(rm0, __shfl_xor_sync(0xffffffffu, rm0, 2));
        rm1 = fmaxf(rm1, __shfl_xor_sync(0xffffffffu, rm1, 1));
        rm1 = fmaxf(rm1, __shfl_xor_sync(0xffffffffu, rm1, 2));

        const float mn0 = fmaxf(m0, rm0), mn1 = fmaxf(m1, rm1);
        const float a0 = __expf(m0 - mn0), a1 = __expf(m1 - mn1);
        m0 = mn0; m1 = mn1;

        float rs0 = 0.f, rs1 = 0.f;
        #pragma unroll
        for (int nt = 0; nt < 8; nt++) {
            sacc[nt][0] = __expf(sacc[nt][0] - m0);
            sacc[nt][1] = __expf(sacc[nt][1] - m0);
            sacc[nt][2] = __expf(sacc[nt][2] - m1);
            sacc[nt][3] = __expf(sacc[nt][3] - m1);
            rs0 += sacc[nt][0] + sacc[nt][1];
            rs1 += sacc[nt][2] + sacc[nt][3];
        }
        rs0 += __shfl_xor_sync(0xffffffffu, rs0, 1);
        rs0 += __shfl_xor_sync(0xffffffffu, rs0, 2);
        rs1 += __shfl_xor_sync(0xffffffffu, rs1, 1);
        rs1 += __shfl_xor_sync(0xffffffffu, rs1, 2);
        l0 = l0 * a0 + rs0;
        l1 = l1 * a1 + rs1;

        #pragma unroll
        for (int nt = 0; nt < 10; nt++) {
            oacc[nt][0] *= a0; oacc[nt][1] *= a0;
            oacc[nt][2] *= a1; oacc[nt][3] *= a1;
        }

        // O += P V  (P a-frags from sacc: chunk t = n-tiles 2t, 2t+1)
        {
            const uint32_t* vs32 = reinterpret_cast<const uint32_t*>(Vs);
            #pragma unroll
            for (int t = 0; t < 4; t++) {
                uint32_t pf[4];
                pf[0] = pack2(sacc[2 * t][0],     sacc[2 * t][1]);
                pf[1] = pack2(sacc[2 * t][2],     sacc[2 * t][3]);
                pf[2] = pack2(sacc[2 * t + 1][0], sacc[2 * t + 1][1]);
                pf[3] = pack2(sacc[2 * t + 1][2], sacc[2 * t + 1][3]);
                const int k2 = t * 8 + tig;
                #pragma unroll
                for (int nt = 0; nt < 10; nt++) {
                    const int nn = nt * 8 + g;
                    uint32_t bf[2];
                    bf[0] = vs32[nn * FVP2 + k2];
                    bf[1] = vs32[nn * FVP2 + k2 + 4];
                    mma_f16(oacc[nt], pf, bf);
                }
            }
        }
    }

    // finalize: O / l, write fp16 (full 80 cols)
    const float il0 = 1.f / l0, il1 = 1.f / l1;
    const int r0 = i0 + wq + g, r1 = r0 + 8;
    #pragma unroll
    for (int nt = 0; nt < 10; nt++) {
        const int c = nt * 8 + 2 * tig;
        *reinterpret_cast<uint32_t*>(ob + (size_t)r0 * Cdim + c) =
            pack2(oacc[nt][0] * il0, oacc[nt][1] * il0);
        *reinterpret_cast<uint32_t*>(ob + (size_t)r1 * Cdim + c) =
            pack2(oacc[nt][2] * il1, oacc[nt][3] * il1);
    }
}

// ---------------- GEGLU (fp16 in/out, fp32 math) ----------------
__device__ __forceinline__ float geglu_one(float xh, float g)
{
    const float t = tanhf(g * 0.7978845608f * (1.f + 0.044715f * g * g));
    return xh * 0.5f * g * (1.f + t);
}

__global__ void geglu_h(const __half* __restrict__ ff, __half* __restrict__ out)
{
    const size_t idx = (size_t)blockIdx.x * blockDim.x + threadIdx.x;
    if (idx >= (size_t)Mrows * (FFH / 8)) return;
    const size_t row = idx / (FFH / 8);
    const int c8 = (int)(idx % (FFH / 8)) * 8;
    const uint4 xh4 = *reinterpret_cast<const uint4*>(ff + row * FFD + c8);
    const uint4 gt4 = *reinterpret_cast<const uint4*>(ff + row * FFD + FFH + c8);
    const __half2* xh = reinterpret_cast<const __half2*>(&xh4);
    const __half2* gt = reinterpret_cast<const __half2*>(&gt4);
    uint4 o4;
    uint32_t* oh = reinterpret_cast<uint32_t*>(&o4);
    #pragma unroll
    for (int i = 0; i < 4; i++) {
        const float2 xf = __half22float2(xh[i]);
        const float2 gf = __half22float2(gt[i]);
        oh[i] = pack2(geglu_one(xf.x, gf.x), geglu_one(xf.y, gf.y));
    }
    *reinterpret_cast<uint4*>(out + row * FFH + c8) = o4;
}

// ---------------- host orchestration ----------------
extern "C" void kernel_launch(void* const* d_in, const int* in_sizes, int n_in,
                              void* d_out, int out_size)
{
    (void)in_sizes; (void)n_in; (void)out_size;
    const float* x     = (const float*)d_in[0];
    const float* ctx   = (const float*)d_in[1];
    const float* gn_g  = (const float*)d_in[2];
    const float* gn_b  = (const float*)d_in[3];
    const float* piw   = (const float*)d_in[4];
    const float* pib   = (const float*)d_in[5];
    const float* ln1g  = (const float*)d_in[6];
    const float* ln1b  = (const float*)d_in[7];
    const float* a1q   = (const float*)d_in[8];
    const float* a1k   = (const float*)d_in[9];
    const float* a1v   = (const float*)d_in[10];
    const float* a1o   = (const float*)d_in[11];
    const float* a1ob  = (const float*)d_in[12];
    const float* ln2g  = (const float*)d_in[13];
    const float* ln2b  = (const float*)d_in[14];
    const float* a2q   = (const float*)d_in[15];
    const float* a2k   = (const float*)d_in[16];
    const float* a2v   = (const float*)d_in[17];
    const float* a2o   = (const float*)d_in[18];
    const float* a2ob  = (const float*)d_in[19];
    const float* ln3g  = (const float*)d_in[20];
    const float* ln3b  = (const float*)d_in[21];
    const float* ff1w  = (const float*)d_in[22];
    const float* ff1b  = (const float*)d_in[23];
    const float* ff2w  = (const float*)d_in[24];
    const float* ff2b  = (const float*)d_in[25];
    const float* prw   = (const float*)d_in[26];
    const float* prb   = (const float*)d_in[27];
    float* out = (float*)d_out;

    float *y, *t;
    __half *ln16, *q16, *at16, *t16, *ctx16, *qkv16, *kv16, *ff16, *gg16;
    __half *piwT, *wpT, *a2qT, *wcT, *a1oT, *a2oT, *ff1T, *ff2T, *prwT;
    cudaGetSymbolAddress((void**)&y,    g_y);
    cudaGetSymbolAddress((void**)&t,    g_t);
    cudaGetSymbolAddress((void**)&ln16, g_ln16);
    cudaGetSymbolAddress((void**)&q16,  g_q16);
    cudaGetSymbolAddress((void**)&at16, g_at16);
    cudaGetSymbolAddress((void**)&t16,  g_t16);
    cudaGetSymbolAddress((void**)&ctx16,g_ctx16);
    cudaGetSymbolAddress((void**)&qkv16,g_qkv16);
    cudaGetSymbolAddress((void**)&kv16, g_kv16);
    cudaGetSymbolAddress((void**)&ff16, g_ff16);
    cudaGetSymbolAddress((void**)&gg16, g_gg16);
    cudaGetSymbolAddress((void**)&piwT, g_piwT);
    cudaGetSymbolAddress((void**)&wpT,  g_wpT);
    cudaGetSymbolAddress((void**)&a2qT, g_a2qT);
    cudaGetSymbolAddress((void**)&wcT,  g_wcT);
    cudaGetSymbolAddress((void**)&a1oT, g_a1oT);
    cudaGetSymbolAddress((void**)&a2oT, g_a2oT);
    cudaGetSymbolAddress((void**)&ff1T, g_ff1T);
    cudaGetSymbolAddress((void**)&ff2T, g_ff2T);
    cudaGetSymbolAddress((void**)&prwT, g_prwT);

    cudaFuncSetAttribute(hgemm_kernel,
                         cudaFuncAttributeMaxDynamicSharedMemorySize, GEMM_SMEM);

    // ---- fused weight transpose+convert (one launch) + ctx convert ----
    wTall_kernel<<<WT_TOTAL, 256>>>(piw, a1q, a1k, a1v, a2q, a1o, a2o, prw,
                                    a2k, a2v, ff1w, ff2w,
                                    piwT, wpT, a2qT, a1oT, a2oT, prwT,
                                    wcT, ff1T, ff2T);
    f2h_kernel<<<(MCTX * CTXD / 4 + 255) / 256, 256>>>(ctx, ctx16, MCTX * CTXD / 4);

    const dim3 gemm640(Cdim / 128, Mrows / 128);
    const dim3 gemmQKV(1920 / 128, Mrows / 128);
    const dim3 gemmKV(1280 / 128, (MCTX + 127) / 128);
    const dim3 gemmFF(FFD / 128, Mrows / 128);

    // y = proj_in(group_norm(x))
    groupnorm_kernel<<<Bn * 32, 256>>>(x, gn_g, gn_b, ln16);
    hgemm_kernel<<<gemm640, 256, GEMM_SMEM>>>(ln16, piwT, pib, nullptr, y, nullptr,
                                              Mrows, Cdim, Cdim);

    // self attention (fused QKV + flash)
    layernorm_kernel<<<Mrows / 8, 256>>>(y, ln1g, ln1b, ln16, Mrows);
    hgemm_kernel<<<gemmQKV, 256, GEMM_SMEM>>>(ln16, wpT, nullptr, nullptr, nullptr, qkv16,
                                              Mrows, 1920, Cdim);
    flash_attn<<<dim3(Sq / 64, 64), 128>>>(qkv16, qkv16 + 640, qkv16 + 1280, at16,
                                           Sq, 1920, 1920, Sq);
    hgemm_kernel<<<gemm640, 256, GEMM_SMEM>>>(at16, a1oT, a1ob, y, t, nullptr,
                                              Mrows, Cdim, Cdim);

    // cross attention (fused KV + flash)
    layernorm_kernel<<<Mrows / 8, 256>>>(t, ln2g, ln2b, ln16, Mrows);
    hgemm_kernel<<<gemmKV, 256, GEMM_SMEM>>>(ctx16, wcT, nullptr, nullptr, nullptr, kv16,
                                             MCTX, 1280, CTXD);
    hgemm_kernel<<<gemm640, 256, GEMM_SMEM>>>(ln16, a2qT, nullptr, nullptr, nullptr, q16,
                                              Mrows, Cdim, Cdim);
    flash_attn<<<dim3(Sq / 64, 64), 128>>>(q16, kv16, kv16 + 640, at16,
                                           Tctx, Cdim, 1280, Tctx);
    hgemm_kernel<<<gemm640, 256, GEMM_SMEM>>>(at16, a2oT, a2ob, t, t, nullptr,
                                              Mrows, Cdim, Cdim);

    // GEGLU feed-forward (ff2 writes fp32 t and fp16 t16 in one pass)
    layernorm_kernel<<<Mrows / 8, 256>>>(t, ln3g, ln3b, ln16, Mrows);
    hgemm_kernel<<<gemmFF, 256, GEMM_SMEM>>>(ln16, ff1T, ff1b, nullptr, nullptr, ff16,
                                             Mrows, FFD, Cdim);
    geglu_h<<<(Mrows * (FFH / 8) + 255) / 256, 256>>>(ff16, gg16);
    hgemm_kernel<<<gemm640, 256, GEMM_SMEM>>>(gg16, ff2T, ff2b, t, t, t16,
                                              Mrows, Cdim, FFH);

    // proj_out + input residual
    hgemm_kernel<<<gemm640, 256, GEMM_SMEM>>>(t16, prwT, prb, x, out, nullptr,
                                              Mrows, Cdim, Cdim);
}

// round 17
// speedup vs baseline: 1.0525x; 1.0525x over previous
#include <cuda_runtime.h>
#include <cuda_fp16.h>
#include <math.h>
#include <stdint.h>

// ---------------- problem dims ----------------
#define Bn    8
#define Sq    1024
#define Cdim  640
#define Tctx  77
#define CTXD  768
#define NHEAD 8
#define HSZ   80
#define FFD   5120
#define FFH   2560
#define Mrows (Bn * Sq)      // 8192
#define MCTX  (Bn * Tctx)    // 616

// ---------------- scratch ----------------
__device__ float  g_y   [(size_t)Mrows * Cdim];
__device__ float  g_t   [(size_t)Mrows * Cdim];
__device__ __half g_ln16[(size_t)Mrows * Cdim];
__device__ __half g_q16 [(size_t)Mrows * Cdim];
__device__ __half g_at16[(size_t)Mrows * Cdim];
__device__ __half g_t16 [(size_t)Mrows * Cdim];
__device__ __half g_ctx16[(size_t)MCTX * CTXD];
__device__ __half g_qkv16[(size_t)Mrows * 1920];
__device__ __half g_kv16 [(size_t)MCTX * 1280];
__device__ __half g_ff16 [(size_t)Mrows * FFD];
__device__ __half g_gg16 [(size_t)Mrows * FFH];
// transposed fp16 weights [N][K]
__device__ __half g_piwT[(size_t)Cdim * Cdim];
__device__ __half g_wpT [(size_t)1920 * Cdim];
__device__ __half g_a2qT[(size_t)Cdim * Cdim];
__device__ __half g_wcT [(size_t)1280 * CTXD];
__device__ __half g_a1oT[(size_t)Cdim * Cdim];
__device__ __half g_a2oT[(size_t)Cdim * Cdim];
__device__ __half g_ff1T[(size_t)FFD * Cdim];
__device__ __half g_ff2T[(size_t)Cdim * FFH];
__device__ __half g_prwT[(size_t)Cdim * Cdim];

// ---------------- helpers ----------------
__device__ __forceinline__ void mma_f16(float* c, const uint32_t* a, const uint32_t* b)
{
    asm volatile(
        "mma.sync.aligned.m16n8k16.row.col.f32.f16.f16.f32 "
        "{%0,%1,%2,%3}, {%4,%5,%6,%7}, {%8,%9}, {%0,%1,%2,%3};"
        : "+f"(c[0]), "+f"(c[1]), "+f"(c[2]), "+f"(c[3])
        : "r"(a[0]), "r"(a[1]), "r"(a[2]), "r"(a[3]), "r"(b[0]), "r"(b[1]));
}

__device__ __forceinline__ void cp16(uint32_t dst, const void* src, bool pred)
{
    const int sz = pred ? 16 : 0;
    asm volatile("cp.async.cg.shared.global [%0], [%1], 16, %2;\n"
                 :: "r"(dst), "l"(src), "r"(sz));
}
__device__ __forceinline__ void cp_commit() { asm volatile("cp.async.commit_group;\n"); }
template <int N>
__device__ __forceinline__ void cp_wait() { asm volatile("cp.async.wait_group %0;\n" :: "n"(N)); }

__device__ __forceinline__ uint32_t pack2(float a, float b)
{
    __half2 h = __floats2half2_rn(a, b);
    return *reinterpret_cast<uint32_t*>(&h);
}

// ---------------- fused weight transpose+convert: 12 jobs, one launch ----------------
#define SQ_TILES   400
#define WC_TILES   480
#define FF1_TILES  3200
#define FF2_TILES  1600
#define JOB_SQ_END   (8 * SQ_TILES)
#define JOB_WC_END   (JOB_SQ_END + 2 * WC_TILES)
#define JOB_FF1_END  (JOB_WC_END + FF1_TILES)
#define WT_TOTAL     (JOB_FF1_END + FF2_TILES)

__global__ void wTall_kernel(
    const float* __restrict__ piw, const float* __restrict__ a1q,
    const float* __restrict__ a1k, const float* __restrict__ a1v,
    const float* __restrict__ a2q, const float* __restrict__ a1o,
    const float* __restrict__ a2o, const float* __restrict__ prw,
    const float* __restrict__ a2k, const float* __restrict__ a2v,
    const float* __restrict__ ff1w, const float* __restrict__ ff2w,
    __half* __restrict__ piwT, __half* __restrict__ wpT,
    __half* __restrict__ a2qT, __half* __restrict__ a1oT,
    __half* __restrict__ a2oT, __half* __restrict__ prwT,
    __half* __restrict__ wcT,  __half* __restrict__ ff1T,
    __half* __restrict__ ff2T)
{
    const int bid = blockIdx.x;
    const float* src;
    __half* dst;
    int K, N, t;
    if (bid < JOB_SQ_END) {
        const int j = bid / SQ_TILES;
        t = bid % SQ_TILES;
        K = Cdim; N = Cdim;
        const float* srcs[8] = { piw, a1q, a1k, a1v, a2q, a1o, a2o, prw };
        __half* dsts[8] = { piwT, wpT, wpT + (size_t)640 * Cdim,
                            wpT + (size_t)1280 * Cdim, a2qT, a1oT, a2oT, prwT };
        src = srcs[j]; dst = dsts[j];
    } else if (bid < JOB_WC_END) {
        const int j = (bid - JOB_SQ_END) / WC_TILES;
        t = (bid - JOB_SQ_END) % WC_TILES;
        K = CTXD; N = Cdim;
        src = j ? a2v : a2k;
        dst = wcT + (size_t)j * 640 * CTXD;
    } else if (bid < JOB_FF1_END) {
        t = bid - JOB_WC_END;
        K = Cdim; N = FFD;
        src = ff1w; dst = ff1T;
    } else {
        t = bid - JOB_FF1_END;
        K = FFH; N = Cdim;
        src = ff2w; dst = ff2T;
    }

    __shared__ float ts[32][33];
    const int ntx = N / 32;
    const int kt = (t / ntx) * 32, nt = (t % ntx) * 32;
    const int tx = threadIdx.x & 31, ty = threadIdx.x >> 5;
    #pragma unroll
    for (int r = ty; r < 32; r += 8)
        ts[r][tx] = src[(size_t)(kt + r) * N + nt + tx];
    __syncthreads();
    #pragma unroll
    for (int r = ty; r < 32; r += 8)
        dst[(size_t)(nt + r) * K + kt + tx] = __float2half(ts[tx][r]);
}

// ---------------- fp32 -> fp16 (count multiple of 4) ----------------
__global__ void f2h_kernel(const float* __restrict__ in, __half* __restrict__ out, int n4)
{
    const int i = blockIdx.x * blockDim.x + threadIdx.x;
    if (i >= n4) return;
    const float4 v = *reinterpret_cast<const float4*>(in + (size_t)i * 4);
    uint2 u; u.x = pack2(v.x, v.y); u.y = pack2(v.z, v.w);
    *reinterpret_cast<uint2*>(out + (size_t)i * 4) = u;
}

// ---------------- GroupNorm (fp32 in, fp16 out) ----------------
__global__ void groupnorm_kernel(const float* __restrict__ x,
                                 const float* __restrict__ gamma,
                                 const float* __restrict__ beta,
                                 __half* __restrict__ out)
{
    const int b = blockIdx.x >> 5;
    const int g = blockIdx.x & 31;
    const float* base = x + (size_t)b * Sq * Cdim + g * 20;
    float sum = 0.f, sq = 0.f;
    for (int idx = threadIdx.x; idx < Sq * 20; idx += 256) {
        int hw = idx / 20, c = idx % 20;
        float v = base[(size_t)hw * Cdim + c];
        sum += v; sq += v * v;
    }
    #pragma unroll
    for (int o = 16; o > 0; o >>= 1) {
        sum += __shfl_xor_sync(0xffffffffu, sum, o);
        sq  += __shfl_xor_sync(0xffffffffu, sq,  o);
    }
    __shared__ float s1[8], s2[8];
    const int wid = threadIdx.x >> 5, lane = threadIdx.x & 31;
    if (lane == 0) { s1[wid] = sum; s2[wid] = sq; }
    __syncthreads();
    float tot = 0.f, totq = 0.f;
    #pragma unroll
    for (int i = 0; i < 8; i++) { tot += s1[i]; totq += s2[i]; }
    const float mean = tot * (1.f / 20480.f);
    const float var  = totq * (1.f / 20480.f) - mean * mean;
    const float rstd = rsqrtf(var + 1e-5f);
    __half* ob = out + (size_t)b * Sq * Cdim + g * 20;
    for (int idx = threadIdx.x; idx < Sq * 20; idx += 256) {
        int hw = idx / 20, c = idx % 20;
        float v = base[(size_t)hw * Cdim + c];
        ob[(size_t)hw * Cdim + c] =
            __float2half((v - mean) * rstd * gamma[g * 20 + c] + beta[g * 20 + c]);
    }
}

// ---------------- LayerNorm (fp32 in, fp16 out) ----------------
__global__ void layernorm_kernel(const float* __restrict__ x,
                                 const float* __restrict__ g,
                                 const float* __restrict__ b,
                                 __half* __restrict__ out, int rows)
{
    const int w = (blockIdx.x << 3) + (threadIdx.x >> 5);
    if (w >= rows) return;
    const int lane = threadIdx.x & 31;
    const float* row = x + (size_t)w * Cdim;
    float4 v[5];
    float sum = 0.f, sq = 0.f;
    #pragma unroll
    for (int p = 0; p < 5; p++) {
        v[p] = *reinterpret_cast<const float4*>(row + (lane + 32 * p) * 4);
        sum += v[p].x + v[p].y + v[p].z + v[p].w;
        sq  += v[p].x * v[p].x + v[p].y * v[p].y + v[p].z * v[p].z + v[p].w * v[p].w;
    }
    #pragma unroll
    for (int o = 16; o > 0; o >>= 1) {
        sum += __shfl_xor_sync(0xffffffffu, sum, o);
        sq  += __shfl_xor_sync(0xffffffffu, sq,  o);
    }
    const float mean = sum * (1.f / 640.f);
    const float var  = sq * (1.f / 640.f) - mean * mean;
    const float rstd = rsqrtf(var + 1e-5f);
    __half* orow = out + (size_t)w * Cdim;
    #pragma unroll
    for (int p = 0; p < 5; p++) {
        const int off = (lane + 32 * p) * 4;
        const float4 g4 = *reinterpret_cast<const float4*>(g + off);
        const float4 b4 = *reinterpret_cast<const float4*>(b + off);
        uint2 u;
        u.x = pack2((v[p].x - mean) * rstd * g4.x + b4.x,
                    (v[p].y - mean) * rstd * g4.y + b4.y);
        u.y = pack2((v[p].z - mean) * rstd * g4.z + b4.z,
                    (v[p].w - mean) * rstd * g4.w + b4.w);
        *reinterpret_cast<uint2*>(orow + off) = u;
    }
}

// ---------------- pipelined FP16 GEMM (BK = 32 halfs, proven R15 shape) ----------------
#define HP   40
#define HP2  20
#define STGH (128 * HP)
#define STGB (STGH * 2)
#define NSTAGE 3
#define GEMM_SMEM (NSTAGE * 2 * STGB)

__global__ __launch_bounds__(256, 2)
void hgemm_kernel(const __half* __restrict__ A, const __half* __restrict__ Bt,
                  const float* __restrict__ bias, const float* __restrict__ Res,
                  float* __restrict__ C32, __half* __restrict__ C16,
                  int M, int N, int K)
{
    extern __shared__ __half smem[];
    __half* As = smem;
    __half* Bs = smem + NSTAGE * STGH;
    const int tid  = threadIdx.x;
    const int lane = tid & 31, warp = tid >> 5;
    const int g = lane >> 2, tig = lane & 3;
    const int wm = (warp >> 2) * 64;
    const int wn = (warp & 3) * 32;
    const int row0 = blockIdx.y * 128, col0 = blockIdx.x * 128;

    const int srow = tid >> 1, soff = (tid & 1) * 16;
    const bool arow_ok = (row0 + srow) < M;
    const __half* agp = A  + (size_t)(row0 + srow) * K + soff;
    const __half* bgp = Bt + (size_t)(col0 + srow) * K + soff;
    const uint32_t as_d = (uint32_t)__cvta_generic_to_shared(As + srow * HP + soff);
    const uint32_t bs_d = (uint32_t)__cvta_generic_to_shared(Bs + srow * HP + soff);

    float acc[4][4][4];
    #pragma unroll
    for (int mt = 0; mt < 4; mt++)
        #pragma unroll
        for (int nt = 0; nt < 4; nt++)
            #pragma unroll
            for (int i = 0; i < 4; i++) acc[mt][nt][i] = 0.f;

    const int KT = K >> 5;

    #pragma unroll
    for (int p = 0; p < 2; p++) {
        if (p < KT) {
            const __half* ag = agp + p * 32;
            const __half* bg = bgp + p * 32;
            #pragma unroll
            for (int l = 0; l < 2; l++) cp16(as_d + (uint32_t)(p * STGB) + l * 16, ag + l * 8, arow_ok);
            #pragma unroll
            for (int l = 0; l < 2; l++) cp16(bs_d + (uint32_t)(p * STGB) + l * 16, bg + l * 8, true);
        }
        cp_commit();
    }

    int s = 0, sw = 2;
    for (int kt = 0; kt < KT; kt++) {
        cp_wait<1>();
        __syncthreads();

        if (kt + 2 < KT) {
            const __half* ag = agp + (kt + 2) * 32;
            const __half* bg = bgp + (kt + 2) * 32;
            const uint32_t ad = as_d + (uint32_t)(sw * STGB);
            const uint32_t bd = bs_d + (uint32_t)(sw * STGB);
            #pragma unroll
            for (int l = 0; l < 2; l++) cp16(ad + l * 16, ag + l * 8, arow_ok);
            #pragma unroll
            for (int l = 0; l < 2; l++) cp16(bd + l * 16, bg + l * 8, true);
        }
        cp_commit();

        const uint32_t* as32 = reinterpret_cast<const uint32_t*>(As + s * STGH);
        const uint32_t* bs32 = reinterpret_cast<const uint32_t*>(Bs + s * STGH);
        #pragma unroll
        for (int ks = 0; ks < 2; ks++) {
            const int k2 = ks * 8 + tig;
            uint32_t af[4][4];
            #pragma unroll
            for (int mt = 0; mt < 4; mt++) {
                const int m = wm + mt * 16 + g;
                af[mt][0] = as32[m * HP2 + k2];
                af[mt][1] = as32[(m + 8) * HP2 + k2];
                af[mt][2] = as32[m * HP2 + k2 + 4];
                af[mt][3] = as32[(m + 8) * HP2 + k2 + 4];
            }
            uint32_t bf[4][2];
            #pragma unroll
            for (int nt = 0; nt < 4; nt++) {
                const int n = wn + nt * 8 + g;
                bf[nt][0] = bs32[n * HP2 + k2];
                bf[nt][1] = bs32[n * HP2 + k2 + 4];
            }
            #pragma unroll
            for (int mt = 0; mt < 4; mt++)
                #pragma unroll
                for (int nt = 0; nt < 4; nt++)
                    mma_f16(acc[mt][nt], af[mt], bf[nt]);
        }

        s = (s == NSTAGE - 1) ? 0 : s + 1;
        sw = (sw == NSTAGE - 1) ? 0 : sw + 1;
    }

    #pragma unroll
    for (int mt = 0; mt < 4; mt++) {
        const int r0 = row0 + wm + mt * 16 + g;
        const int r1 = r0 + 8;
        #pragma unroll
        for (int nt = 0; nt < 4; nt++) {
            const int c = col0 + wn + nt * 8 + 2 * tig;
            float2 v0 = make_float2(acc[mt][nt][0], acc[mt][nt][1]);
            float2 v1 = make_float2(acc[mt][nt][2], acc[mt][nt][3]);
            if (bias) {
                const float2 bb = *reinterpret_cast<const float2*>(bias + c);
                v0.x += bb.x; v0.y += bb.y;
                v1.x += bb.x; v1.y += bb.y;
            }
            if (r0 < M) {
                if (Res) {
                    const float2 rv = *reinterpret_cast<const float2*>(Res + (size_t)r0 * N + c);
                    v0.x += rv.x; v0.y += rv.y;
                }
                if (C32) *reinterpret_cast<float2*>(C32 + (size_t)r0 * N + c) = v0;
                if (C16) *reinterpret_cast<uint32_t*>(C16 + (size_t)r0 * N + c) = pack2(v0.x, v0.y);
            }
            if (r1 < M) {
                if (Res) {
                    const float2 rv = *reinterpret_cast<const float2*>(Res + (size_t)r1 * N + c);
                    v1.x += rv.x; v1.y += rv.y;
                }
                if (C32) *reinterpret_cast<float2*>(C32 + (size_t)r1 * N + c) = v1;
                if (C16) *reinterpret_cast<uint32_t*>(C16 + (size_t)r1 * N + c) = pack2(v1.x, v1.y);
            }
        }
    }
}

// ---------------- fused flash attention (fp16 in/out, fp32 softmax state) ----------------
#define FQP  88
#define FQP2 44
#define FVP  72
#define FVP2 36
__global__ __launch_bounds__(128)
void flash_attn(const __half* __restrict__ Q, const __half* __restrict__ K,
                const __half* __restrict__ V, __half* __restrict__ O,
                int Tk, int qstr, int kstr, int kSeq)
{
    __shared__ __half Qs[64 * FQP];
    __shared__ __half Ks[64 * FQP];
    __shared__ __half Vs[80 * FVP];

    const int bh = blockIdx.y, b = bh >> 3, n = bh & 7;
    const __half* qb = Q + (size_t)b * Sq * qstr + n * HSZ;
    const __half* kb = K + (size_t)b * kSeq * kstr + n * HSZ;
    const __half* vb = V + (size_t)b * kSeq * kstr + n * HSZ;
    __half* ob = O + (size_t)b * Sq * Cdim + n * HSZ;
    const int i0 = blockIdx.x * 64;
    const int tid = threadIdx.x;
    const int lane = tid & 31, warp = tid >> 5;
    const int g = lane >> 2, tig = lane & 3;
    const int wq = warp * 16;

    for (int e = tid; e < 64 * 10; e += 128) {
        const int r = e / 10, c8 = (e % 10) * 8;
        *reinterpret_cast<uint4*>(&Qs[r * FQP + c8]) =
            *reinterpret_cast<const uint4*>(qb + (size_t)(i0 + r) * qstr + c8);
    }
    __syncthreads();

    uint32_t qf[5][4];
    {
        const uint32_t* qs32 = reinterpret_cast<const uint32_t*>(Qs);
        #pragma unroll
        for (int ks = 0; ks < 5; ks++) {
            const int k2 = ks * 8 + tig;
            qf[ks][0] = qs32[(wq + g) * FQP2 + k2];
            qf[ks][1] = qs32[(wq + g + 8) * FQP2 + k2];
            qf[ks][2] = qs32[(wq + g) * FQP2 + k2 + 4];
            qf[ks][3] = qs32[(wq + g + 8) * FQP2 + k2 + 4];
        }
    }

    float m0 = -1e30f, m1 = -1e30f, l0 = 0.f, l1 = 0.f;
    float oacc[10][4];
    #pragma unroll
    for (int nt = 0; nt < 10; nt++)
        #pragma unroll
        for (int i = 0; i < 4; i++) oacc[nt][i] = 0.f;

    const float scale = 0.11180339887498949f;
    const int nT = (Tk + 63) / 64;

    for (int jt = 0; jt < nT; jt++) {
        __syncthreads();
        for (int e = tid; e < 64 * 10; e += 128) {
            const int r = e / 10, c8 = (e % 10) * 8;
            uint4 kv = make_uint4(0u, 0u, 0u, 0u);
            if (jt * 64 + r < Tk)
                kv = *reinterpret_cast<const uint4*>(kb + (size_t)(jt * 64 + r) * kstr + c8);
            *reinterpret_cast<uint4*>(&Ks[r * FQP + c8]) = kv;
            uint4 vv = make_uint4(0u, 0u, 0u, 0u);
            if (jt * 64 + r < Tk)
                vv = *reinterpret_cast<const uint4*>(vb + (size_t)(jt * 64 + r) * kstr + c8);
            const __half* vh = reinterpret_cast<const __half*>(&vv);
            #pragma unroll
            for (int i = 0; i < 8; i++)
                Vs[(c8 + i) * FVP + r] = vh[i];
        }
        __syncthreads();

        float sacc[8][4];
        #pragma unroll
        for (int nt = 0; nt < 8; nt++)
            #pragma unroll
            for (int i = 0; i < 4; i++) sacc[nt][i] = 0.f;
        {
            const uint32_t* ks32 = reinterpret_cast<const uint32_t*>(Ks);
            #pragma unroll
            for (int ks = 0; ks < 5; ks++) {
                const int k2 = ks * 8 + tig;
                uint32_t bf[8][2];
                #pragma unroll
                for (int nt = 0; nt < 8; nt++) {
                    const int nn = nt * 8 + g;
                    bf[nt][0] = ks32[nn * FQP2 + k2];
                    bf[nt][1] = ks32[nn * FQP2 + k2 + 4];
                }
                #pragma unroll
                for (int nt = 0; nt < 8; nt++)
                    mma_f16(sacc[nt], qf[ks], bf[nt]);
            }
        }

        float rm0 = -1e30f, rm1 = -1e30f;
        #pragma unroll
        for (int nt = 0; nt < 8; nt++) {
            const int cb = jt * 64 + nt * 8 + 2 * tig;
            sacc[nt][0] = (cb     < Tk) ? sacc[nt][0] * scale : -1e30f;
            sacc[nt][1] = (cb + 1 < Tk) ? sacc[nt][1] * scale : -1e30f;
            sacc[nt][2] = (cb     < Tk) ? sacc[nt][2] * scale : -1e30f;
            sacc[nt][3] = (cb + 1 < Tk) ? sacc[nt][3] * scale : -1e30f;
            rm0 = fmaxf(rm0, fmaxf(sacc[nt][0], sacc[nt][1]));
            rm1 = fmaxf(rm1, fmaxf(sacc[nt][2], sacc[nt][3]));
        }
        rm0 = fmaxf(rm0, __shfl_xor_sync(0xffffffffu, rm0, 1));
        rm0 = fmaxf(rm0, __shfl_xor_sync(0xffffffffu, rm0, 2));
        rm1 = fmaxf(rm1, __shfl_xor_sync(0xffffffffu, rm1, 1));
        rm1 = fmaxf(rm1, __shfl_xor_sync(0xffffffffu, rm1, 2));

        const float mn0 = fmaxf(m0, rm0), mn1 = fmaxf(m1, rm1);
        const float a0 = __expf(m0 - mn0), a1 = __expf(m1 - mn1);
        m0 = mn0; m1 = mn1;

        float rs0 = 0.f, rs1 = 0.f;
        #pragma unroll
        for (int nt = 0; nt < 8; nt++) {
            sacc[nt][0] = __expf(sacc[nt][0] - m0);
            sacc[nt][1] = __expf(sacc[nt][1] - m0);
            sacc[nt][2] = __expf(sacc[nt][2] - m1);
            sacc[nt][3] = __expf(sacc[nt][3] - m1);
            rs0 += sacc[nt][0] + sacc[nt][1];
            rs1 += sacc[nt][2] + sacc[nt][3];
        }
        rs0 += __shfl_xor_sync(0xffffffffu, rs0, 1);
        rs0 += __shfl_xor_sync(0xffffffffu, rs0, 2);
        rs1 += __shfl_xor_sync(0xffffffffu, rs1, 1);
        rs1 += __shfl_xor_sync(0xffffffffu, rs1, 2);
        l0 = l0 * a0 + rs0;
        l1 = l1 * a1 + rs1;

        #pragma unroll
        for (int nt = 0; nt < 10; nt++) {
            oacc[nt][0] *= a0; oacc[nt][1] *= a0;
            oacc[nt][2] *= a1; oacc[nt][3] *= a1;
        }

        {
            const uint32_t* vs32 = reinterpret_cast<const uint32_t*>(Vs);
            #pragma unroll
            for (int t = 0; t < 4; t++) {
                uint32_t pf[4];
                pf[0] = pack2(sacc[2 * t][0],     sacc[2 * t][1]);
                pf[1] = pack2(sacc[2 * t][2],     sacc[2 * t][3]);
                pf[2] = pack2(sacc[2 * t + 1][0], sacc[2 * t + 1][1]);
                pf[3] = pack2(sacc[2 * t + 1][2], sacc[2 * t + 1][3]);
                const int k2 = t * 8 + tig;
                #pragma unroll
                for (int nt = 0; nt < 10; nt++) {
                    const int nn = nt * 8 + g;
                    uint32_t bf[2];
                    bf[0] = vs32[nn * FVP2 + k2];
                    bf[1] = vs32[nn * FVP2 + k2 + 4];
                    mma_f16(oacc[nt], pf, bf);
                }
            }
        }
    }

    const float il0 = 1.f / l0, il1 = 1.f / l1;
    const int r0 = i0 + wq + g, r1 = r0 + 8;
    #pragma unroll
    for (int nt = 0; nt < 10; nt++) {
        const int c = nt * 8 + 2 * tig;
        *reinterpret_cast<uint32_t*>(ob + (size_t)r0 * Cdim + c) =
            pack2(oacc[nt][0] * il0, oacc[nt][1] * il0);
        *reinterpret_cast<uint32_t*>(ob + (size_t)r1 * Cdim + c) =
            pack2(oacc[nt][2] * il1, oacc[nt][3] * il1);
    }
}

// ---------------- GEGLU (fp16 in/out, fp32 math) ----------------
__device__ __forceinline__ float geglu_one(float xh, float g)
{
    const float t = tanhf(g * 0.7978845608f * (1.f + 0.044715f * g * g));
    return xh * 0.5f * g * (1.f + t);
}

__global__ void geglu_h(const __half* __restrict__ ff, __half* __restrict__ out)
{
    const size_t idx = (size_t)blockIdx.x * blockDim.x + threadIdx.x;
    if (idx >= (size_t)Mrows * (FFH / 8)) return;
    const size_t row = idx / (FFH / 8);
    const int c8 = (int)(idx % (FFH / 8)) * 8;
    const uint4 xh4 = *reinterpret_cast<const uint4*>(ff + row * FFD + c8);
    const uint4 gt4 = *reinterpret_cast<const uint4*>(ff + row * FFD + FFH + c8);
    const __half2* xh = reinterpret_cast<const __half2*>(&xh4);
    const __half2* gt = reinterpret_cast<const __half2*>(&gt4);
    uint4 o4;
    uint32_t* oh = reinterpret_cast<uint32_t*>(&o4);
    #pragma unroll
    for (int i = 0; i < 4; i++) {
        const float2 xf = __half22float2(xh[i]);
        const float2 gf = __half22float2(gt[i]);
        oh[i] = pack2(geglu_one(xf.x, gf.x), geglu_one(xf.y, gf.y));
    }
    *reinterpret_cast<uint4*>(out + row * FFH + c8) = o4;
}

// ---------------- host orchestration ----------------
extern "C" void kernel_launch(void* const* d_in, const int* in_sizes, int n_in,
                              void* d_out, int out_size)
{
    (void)in_sizes; (void)n_in; (void)out_size;
    const float* x     = (const float*)d_in[0];
    const float* ctx   = (const float*)d_in[1];
    const float* gn_g  = (const float*)d_in[2];
    const float* gn_b  = (const float*)d_in[3];
    const float* piw   = (const float*)d_in[4];
    const float* pib   = (const float*)d_in[5];
    const float* ln1g  = (const float*)d_in[6];
    const float* ln1b  = (const float*)d_in[7];
    const float* a1q   = (const float*)d_in[8];
    const float* a1k   = (const float*)d_in[9];
    const float* a1v   = (const float*)d_in[10];
    const float* a1o   = (const float*)d_in[11];
    const float* a1ob  = (const float*)d_in[12];
    const float* ln2g  = (const float*)d_in[13];
    const float* ln2b  = (const float*)d_in[14];
    const float* a2q   = (const float*)d_in[15];
    const float* a2k   = (const float*)d_in[16];
    const float* a2v   = (const float*)d_in[17];
    const float* a2o   = (const float*)d_in[18];
    const float* a2ob  = (const float*)d_in[19];
    const float* ln3g  = (const float*)d_in[20];
    const float* ln3b  = (const float*)d_in[21];
    const float* ff1w  = (const float*)d_in[22];
    const float* ff1b  = (const float*)d_in[23];
    const float* ff2w  = (const float*)d_in[24];
    const float* ff2b  = (const float*)d_in[25];
    const float* prw   = (const float*)d_in[26];
    const float* prb   = (const float*)d_in[27];
    float* out = (float*)d_out;

    float *y, *t;
    __half *ln16, *q16, *at16, *t16, *ctx16, *qkv16, *kv16, *ff16, *gg16;
    __half *piwT, *wpT, *a2qT, *wcT, *a1oT, *a2oT, *ff1T, *ff2T, *prwT;
    cudaGetSymbolAddress((void**)&y,    g_y);
    cudaGetSymbolAddress((void**)&t,    g_t);
    cudaGetSymbolAddress((void**)&ln16, g_ln16);
    cudaGetSymbolAddress((void**)&q16,  g_q16);
    cudaGetSymbolAddress((void**)&at16, g_at16);
    cudaGetSymbolAddress((void**)&t16,  g_t16);
    cudaGetSymbolAddress((void**)&ctx16,g_ctx16);
    cudaGetSymbolAddress((void**)&qkv16,g_qkv16);
    cudaGetSymbolAddress((void**)&kv16, g_kv16);
    cudaGetSymbolAddress((void**)&ff16, g_ff16);
    cudaGetSymbolAddress((void**)&gg16, g_gg16);
    cudaGetSymbolAddress((void**)&piwT, g_piwT);
    cudaGetSymbolAddress((void**)&wpT,  g_wpT);
    cudaGetSymbolAddress((void**)&a2qT, g_a2qT);
    cudaGetSymbolAddress((void**)&wcT,  g_wcT);
    cudaGetSymbolAddress((void**)&a1oT, g_a1oT);
    cudaGetSymbolAddress((void**)&a2oT, g_a2oT);
    cudaGetSymbolAddress((void**)&ff1T, g_ff1T);
    cudaGetSymbolAddress((void**)&ff2T, g_ff2T);
    cudaGetSymbolAddress((void**)&prwT, g_prwT);

    cudaFuncSetAttribute(hgemm_kernel,
                         cudaFuncAttributeMaxDynamicSharedMemorySize, GEMM_SMEM);

    // ---- fused weight transpose+convert (one launch) + ctx convert ----
    wTall_kernel<<<WT_TOTAL, 256>>>(piw, a1q, a1k, a1v, a2q, a1o, a2o, prw,
                                    a2k, a2v, ff1w, ff2w,
                                    piwT, wpT, a2qT, a1oT, a2oT, prwT,
                                    wcT, ff1T, ff2T);
    f2h_kernel<<<(MCTX * CTXD / 4 + 255) / 256, 256>>>(ctx, ctx16, MCTX * CTXD / 4);

    const dim3 gemm640(Cdim / 128, Mrows / 128);
    const dim3 gemmQKV(1920 / 128, Mrows / 128);
    const dim3 gemmKV(1280 / 128, (MCTX + 127) / 128);
    const dim3 gemmFF(FFD / 128, Mrows / 128);

    // y = proj_in(group_norm(x))
    groupnorm_kernel<<<Bn * 32, 256>>>(x, gn_g, gn_b, ln16);
    hgemm_kernel<<<gemm640, 256, GEMM_SMEM>>>(ln16, piwT, pib, nullptr, y, nullptr,
                                              Mrows, Cdim, Cdim);

    // self attention (fused QKV + flash)
    layernorm_kernel<<<Mrows / 8, 256>>>(y, ln1g, ln1b, ln16, Mrows);
    hgemm_kernel<<<gemmQKV, 256, GEMM_SMEM>>>(ln16, wpT, nullptr, nullptr, nullptr, qkv16,
                                              Mrows, 1920, Cdim);
    flash_attn<<<dim3(Sq / 64, 64), 128>>>(qkv16, qkv16 + 640, qkv16 + 1280, at16,
                                           Sq, 1920, 1920, Sq);
    hgemm_kernel<<<gemm640, 256, GEMM_SMEM>>>(at16, a1oT, a1ob, y, t, nullptr,
                                              Mrows, Cdim, Cdim);

    // cross attention (fused KV + flash)
    layernorm_kernel<<<Mrows / 8, 256>>>(t, ln2g, ln2b, ln16, Mrows);
    hgemm_kernel<<<gemmKV, 256, GEMM_SMEM>>>(ctx16, wcT, nullptr, nullptr, nullptr, kv16,
                                             MCTX, 1280, CTXD);
    hgemm_kernel<<<gemm640, 256, GEMM_SMEM>>>(ln16, a2qT, nullptr, nullptr, nullptr, q16,
                                              Mrows, Cdim, Cdim);
    flash_attn<<<dim3(Sq / 64, 64), 128>>>(q16, kv16, kv16 + 640, at16,
                                           Tctx, Cdim, 1280, Tctx);
    hgemm_kernel<<<gemm640, 256, GEMM_SMEM>>>(at16, a2oT, a2ob, t, t, nullptr,
                                              Mrows, Cdim, Cdim);

    // GEGLU feed-forward (ff2 writes fp32 t and fp16 t16 in one pass)
    layernorm_kernel<<<Mrows / 8, 256>>>(t, ln3g, ln3b, ln16, Mrows);
    hgemm_kernel<<<gemmFF, 256, GEMM_SMEM>>>(ln16, ff1T, ff1b, nullptr, nullptr, ff16,
                                             Mrows, FFD, Cdim);
    geglu_h<<<(Mrows * (FFH / 8) + 255) / 256, 256>>>(ff16, gg16);
    hgemm_kernel<<<gemm640, 256, GEMM_SMEM>>>(gg16, ff2T, ff2b, t, t, t16,
                                              Mrows, Cdim, FFH);

    // proj_out + input residual
    hgemm_kernel<<<gemm640, 256, GEMM_SMEM>>>(t16, prwT, prb, x, out, nullptr,
                                              Mrows, Cdim, Cdim);
}